// round 3
// baseline (speedup 1.0000x reference)
#include <cuda_runtime.h>
#include <cstdint>

// Unfold (im2col) — warp-per-2-rows shuffle kernel with streaming stores.
// x: [16, 64, 112, 112] f32 ; out: [16, 576, 112, 112] f32
// out[n, c*9 + kh*3 + kw, h, w] = x[n, c, h+kh-1, w+kw-1] (0 outside)
//
// One warp per (n, c, h-pair). Lanes 0..27 own 4 consecutive w (float4).
// Load rows h0-1..h0+2 (4 aligned LDG.128), build kw=-1/+1 shifts via shfl,
// emit 18 aligned STG.128 with evict-first (.cs) policy so the 462MB output
// stream doesn't thrash the L2-resident 51MB input.

#define HWDIM 112
#define PLANE (HWDIM * HWDIM)   // 12544
#define HPAIRS 56

__global__ __launch_bounds__(256) void unfold_kernel(
    const float* __restrict__ x, float* __restrict__ out)
{
    const int warp = (blockIdx.x * blockDim.x + threadIdx.x) >> 5;
    const int lane = threadIdx.x & 31;

    // warp -> (n, c, hpair); launched exactly 16*64*56 warps
    int hp = warp % HPAIRS;
    int t  = warp / HPAIRS;
    int c  = t & 63;
    int n  = t >> 6;
    const int h0 = hp * 2;

    const bool wok = lane < 28;
    const int w0 = lane * 4;

    const float* plane = x + (int64_t)(n * 64 + c) * PLANE;

    // rows h0-1, h0, h0+1, h0+2
    float4 r[4];
#pragma unroll
    for (int i = 0; i < 4; ++i) {
        const int ih = h0 - 1 + i;
        if (wok && (unsigned)ih < HWDIM)
            r[i] = *reinterpret_cast<const float4*>(plane + ih * HWDIM + w0);
        else
            r[i] = make_float4(0.f, 0.f, 0.f, 0.f);
    }

    // shifted variants per row
    float4 vm[4], vp[4];
#pragma unroll
    for (int i = 0; i < 4; ++i) {
        float pw = __shfl_up_sync(0xFFFFFFFFu, r[i].w, 1);
        if (lane == 0) pw = 0.f;                              // left pad
        float nx = __shfl_down_sync(0xFFFFFFFFu, r[i].x, 1);  // lane27 gets 0
        vm[i] = make_float4(pw, r[i].x, r[i].y, r[i].z);      // kw = -1
        vp[i] = make_float4(r[i].y, r[i].z, r[i].w, nx);      // kw = +1
    }

    float* obase = out + ((int64_t)(n * 576 + c * 9) * HWDIM + h0) * HWDIM + w0;

    if (wok) {
#pragma unroll
        for (int j = 0; j < 2; ++j) {          // output row h0+j
#pragma unroll
            for (int i = 0; i < 3; ++i) {      // kh = i-1 -> input row idx i+j
                float* p = obase + (int64_t)(i * 3) * PLANE + j * HWDIM;
                __stcs(reinterpret_cast<float4*>(p),             vm[i + j]);
                __stcs(reinterpret_cast<float4*>(p + PLANE),     r[i + j]);
                __stcs(reinterpret_cast<float4*>(p + 2 * PLANE), vp[i + j]);
            }
        }
    }
}

extern "C" void kernel_launch(void* const* d_in, const int* in_sizes, int n_in,
                              void* d_out, int out_size)
{
    const float* x = (const float*)d_in[0];
    float* out = (float*)d_out;

    const int warps = 16 * 64 * HPAIRS;       // 57344
    const int threads = 256;                  // 8 warps/block
    const int blocks = warps / 8;             // 7168, exact
    unfold_kernel<<<blocks, threads>>>(x, out);
}